// round 1
// baseline (speedup 1.0000x reference)
#include <cuda_runtime.h>
#include <cuda_bf16.h>
#include <cstdint>
#include <math.h>

// Problem: ex[8192,768], ey[8192,768] fp32.
// C = normalize_rows(ex) @ normalize_rows(ey)^T   [8192, 8192]
// rowmax = max over cols, colmax = max over rows
// lp(c) = -c^2/(2*sigma^2) - log(sigma) - 0.5*log(2*pi),  sigma = 0.8
// out[0] = -sum(exp(lp(rowmax))*lp(rowmax)); out[1] = same for colmax.

#define NROWS 8192
#define KDIM  768

// Scratch (device globals; no allocation allowed)
__device__ __nv_bfloat16 g_Xn[NROWS * KDIM];
__device__ __nv_bfloat16 g_Yn[NROWS * KDIM];
__device__ float g_rowmax[NROWS];
__device__ float g_colmax[NROWS];

__device__ __forceinline__ void atomicMaxF(float* addr, float v) {
    // Standard monotonic-order trick; race-safe for mixed signs.
    if (v >= 0.f) atomicMax((int*)addr, __float_as_int(v));
    else          atomicMin((unsigned int*)addr, __float_as_uint(v));
}

// ---------------------------------------------------------------------------
// Kernel 1: row-normalize fp32 -> bf16.  One block per row (16384 blocks).
// ---------------------------------------------------------------------------
__global__ __launch_bounds__(256) void norm_kernel(const float* __restrict__ ex,
                                                   const float* __restrict__ ey) {
    int b = blockIdx.x;
    const float* src;
    __nv_bfloat16* dst;
    if (b < NROWS) { src = ex + (size_t)b * KDIM; dst = g_Xn + (size_t)b * KDIM; }
    else           { b -= NROWS; src = ey + (size_t)b * KDIM; dst = g_Yn + (size_t)b * KDIM; }

    int tid = threadIdx.x;
    float4 v = make_float4(0.f, 0.f, 0.f, 0.f);
    float ss = 0.f;
    if (tid < 192) {  // 192 * 4 = 768 elements
        v = ((const float4*)src)[tid];
        ss = v.x * v.x + v.y * v.y + v.z * v.z + v.w * v.w;
    }
    #pragma unroll
    for (int o = 16; o > 0; o >>= 1) ss += __shfl_xor_sync(0xffffffffu, ss, o);
    __shared__ float wsum[8];
    if ((tid & 31) == 0) wsum[tid >> 5] = ss;
    __syncthreads();
    float tot = wsum[0] + wsum[1] + wsum[2] + wsum[3] +
                wsum[4] + wsum[5] + wsum[6] + wsum[7];
    float inv = 1.0f / fmaxf(sqrtf(tot), 1e-8f);
    if (tid < 192) {
        dst[tid * 4 + 0] = __float2bfloat16(v.x * inv);
        dst[tid * 4 + 1] = __float2bfloat16(v.y * inv);
        dst[tid * 4 + 2] = __float2bfloat16(v.z * inv);
        dst[tid * 4 + 3] = __float2bfloat16(v.w * inv);
    }
}

// ---------------------------------------------------------------------------
// Kernel 2: init global max arrays (cos >= -1, so -2 is a safe floor).
// ---------------------------------------------------------------------------
__global__ void init_kernel() {
    int t = blockIdx.x * blockDim.x + threadIdx.x;
    if (t < NROWS) { g_rowmax[t] = -2.f; g_colmax[t] = -2.f; }
}

// ---------------------------------------------------------------------------
// Kernel 3: fused bf16 GEMM (mma.sync m16n8k16) + tile row/col max + atomics.
// BM=BN=128, BK=32; 256 threads = 8 warps (4 along M x 2 along N);
// warp tile 32x64 = 2 (m) x 8 (n) mma tiles. 2-stage cp.async pipeline.
// Smem row stride = 40 bf16 = 20 b32 -> conflict-free fragment loads.
// ---------------------------------------------------------------------------
#define BM 128
#define BN 128
#define BK 32
#define SROW   40
#define SROW32 20

__global__ __launch_bounds__(256) void gemm_max_kernel() {
    __shared__ __align__(16) __nv_bfloat16 As[2][BM * SROW];
    __shared__ __align__(16) __nv_bfloat16 Bs[2][BN * SROW];
    __shared__ float srow[BM];
    __shared__ float scol[BN];

    const int tid = threadIdx.x;
    const int m0 = blockIdx.y * BM;
    const int n0 = blockIdx.x * BN;

    if (tid < 128) srow[tid] = -2.f;
    else           scol[tid - 128] = -2.f;

    const int warp = tid >> 5, lane = tid & 31;
    const int g = lane >> 2, tig = lane & 3;
    const int wm = (warp & 3) * 32;   // warp row base in tile
    const int wn = (warp >> 2) * 64;  // warp col base in tile

    float acc[2][8][4];
    #pragma unroll
    for (int a = 0; a < 2; a++)
        #pragma unroll
        for (int b = 0; b < 8; b++)
            #pragma unroll
            for (int c = 0; c < 4; c++) acc[a][b][c] = 0.f;

    auto prefetch = [&](int buf, int k0) {
        #pragma unroll
        for (int r = 0; r < 2; r++) {
            int i   = tid + r * 256;      // 0..511
            int row = i >> 2;             // 0..127
            int seg = i & 3;              // 0..3 -> k offset seg*8
            const __nv_bfloat16* ga = g_Xn + (size_t)(m0 + row) * KDIM + k0 + seg * 8;
            uint32_t sa = (uint32_t)__cvta_generic_to_shared(&As[buf][row * SROW + seg * 8]);
            asm volatile("cp.async.cg.shared.global [%0], [%1], 16;\n" :: "r"(sa), "l"(ga));
            const __nv_bfloat16* gb = g_Yn + (size_t)(n0 + row) * KDIM + k0 + seg * 8;
            uint32_t sb = (uint32_t)__cvta_generic_to_shared(&Bs[buf][row * SROW + seg * 8]);
            asm volatile("cp.async.cg.shared.global [%0], [%1], 16;\n" :: "r"(sb), "l"(gb));
        }
        asm volatile("cp.async.commit_group;\n");
    };

    prefetch(0, 0);
    const int NK = KDIM / BK;  // 24
    for (int it = 0; it < NK; it++) {
        asm volatile("cp.async.wait_group 0;\n");
        __syncthreads();
        int buf = it & 1;
        if (it + 1 < NK) prefetch(buf ^ 1, (it + 1) * BK);

        const uint32_t* A32 = (const uint32_t*)&As[buf][0];
        const uint32_t* B32 = (const uint32_t*)&Bs[buf][0];

        #pragma unroll
        for (int kk = 0; kk < 2; kk++) {
            uint32_t afr[2][4], bfr[8][2];
            #pragma unroll
            for (int mt = 0; mt < 2; mt++) {
                int rb = wm + mt * 16;
                afr[mt][0] = A32[(rb + g)     * SROW32 + kk * 8 + tig];
                afr[mt][1] = A32[(rb + g + 8) * SROW32 + kk * 8 + tig];
                afr[mt][2] = A32[(rb + g)     * SROW32 + kk * 8 + tig + 4];
                afr[mt][3] = A32[(rb + g + 8) * SROW32 + kk * 8 + tig + 4];
            }
            #pragma unroll
            for (int nt = 0; nt < 8; nt++) {
                int cb = wn + nt * 8;
                bfr[nt][0] = B32[(cb + g) * SROW32 + kk * 8 + tig];
                bfr[nt][1] = B32[(cb + g) * SROW32 + kk * 8 + tig + 4];
            }
            #pragma unroll
            for (int mt = 0; mt < 2; mt++)
                #pragma unroll
                for (int nt = 0; nt < 8; nt++) {
                    asm volatile(
                        "mma.sync.aligned.m16n8k16.row.col.f32.bf16.bf16.f32 "
                        "{%0,%1,%2,%3}, {%4,%5,%6,%7}, {%8,%9}, {%0,%1,%2,%3};\n"
                        : "+f"(acc[mt][nt][0]), "+f"(acc[mt][nt][1]),
                          "+f"(acc[mt][nt][2]), "+f"(acc[mt][nt][3])
                        : "r"(afr[mt][0]), "r"(afr[mt][1]), "r"(afr[mt][2]), "r"(afr[mt][3]),
                          "r"(bfr[nt][0]), "r"(bfr[nt][1]));
                }
        }
        __syncthreads();
    }

    // ---- epilogue: row maxes ----
    // Thread owns rows wm + mt*16 + g + p*8, cols spread over tig lanes.
    #pragma unroll
    for (int mt = 0; mt < 2; mt++)
        #pragma unroll
        for (int p = 0; p < 2; p++) {
            float m = -2.f;
            #pragma unroll
            for (int nt = 0; nt < 8; nt++) {
                m = fmaxf(m, acc[mt][nt][p * 2 + 0]);
                m = fmaxf(m, acc[mt][nt][p * 2 + 1]);
            }
            m = fmaxf(m, __shfl_xor_sync(0xffffffffu, m, 1));
            m = fmaxf(m, __shfl_xor_sync(0xffffffffu, m, 2));
            if (tig == 0) atomicMaxF(&srow[wm + mt * 16 + g + p * 8], m);
        }
    // ---- epilogue: col maxes ----
    // Col = wn + nt*8 + tig*2 + q; rows spread over g lanes.
    #pragma unroll
    for (int nt = 0; nt < 8; nt++)
        #pragma unroll
        for (int q = 0; q < 2; q++) {
            float m = fmaxf(fmaxf(acc[0][nt][q], acc[0][nt][2 + q]),
                            fmaxf(acc[1][nt][q], acc[1][nt][2 + q]));
            m = fmaxf(m, __shfl_xor_sync(0xffffffffu, m, 4));
            m = fmaxf(m, __shfl_xor_sync(0xffffffffu, m, 8));
            m = fmaxf(m, __shfl_xor_sync(0xffffffffu, m, 16));
            if (g == 0) atomicMaxF(&scol[wn + nt * 8 + tig * 2 + q], m);
        }

    __syncthreads();
    if (tid < 128) atomicMaxF(&g_rowmax[m0 + tid], srow[tid]);
    else           atomicMaxF(&g_colmax[n0 + tid - 128], scol[tid - 128]);
}

// ---------------------------------------------------------------------------
// Kernel 4: finalize entropy terms.
// ---------------------------------------------------------------------------
__global__ __launch_bounds__(256) void final_kernel(float* __restrict__ out) {
    const float LOG_NORM = -0.69579514f;  // -log(0.8) - 0.5*log(2*pi)
    const float INV2S2   = 0.78125f;      // 1 / (2 * 0.8^2)
    int tid = threadIdx.x;
    float s1 = 0.f, s2 = 0.f;
    for (int i = tid; i < NROWS; i += 256) {
        float c = g_rowmax[i];
        float lp = -(c * c) * INV2S2 + LOG_NORM;
        s1 -= expf(lp) * lp;
        c = g_colmax[i];
        lp = -(c * c) * INV2S2 + LOG_NORM;
        s2 -= expf(lp) * lp;
    }
    #pragma unroll
    for (int o = 16; o > 0; o >>= 1) {
        s1 += __shfl_xor_sync(0xffffffffu, s1, o);
        s2 += __shfl_xor_sync(0xffffffffu, s2, o);
    }
    __shared__ float w1[8], w2[8];
    if ((tid & 31) == 0) { w1[tid >> 5] = s1; w2[tid >> 5] = s2; }
    __syncthreads();
    if (tid == 0) {
        float t1 = 0.f, t2 = 0.f;
        #pragma unroll
        for (int i = 0; i < 8; i++) { t1 += w1[i]; t2 += w2[i]; }
        out[0] = t1;
        out[1] = t2;
    }
}

// ---------------------------------------------------------------------------
extern "C" void kernel_launch(void* const* d_in, const int* in_sizes, int n_in,
                              void* d_out, int out_size) {
    (void)in_sizes; (void)n_in; (void)out_size;
    const float* ex = (const float*)d_in[0];
    const float* ey = (const float*)d_in[1];
    float* out = (float*)d_out;

    norm_kernel<<<2 * NROWS, 256>>>(ex, ey);
    init_kernel<<<(NROWS + 255) / 256, 256>>>();
    dim3 grid(NROWS / BN, NROWS / BM);
    gemm_max_kernel<<<grid, 256>>>();
    final_kernel<<<1, 256>>>(out);
}

// round 3
// speedup vs baseline: 1.2824x; 1.2824x over previous
#include <cuda_runtime.h>
#include <cuda_bf16.h>
#include <cstdint>
#include <math.h>

// C = normalize_rows(ex) @ normalize_rows(ey)^T  [8192 x 8192]
// rowmax/colmax -> entropy terms. mma.sync bf16 GEMM (sm_103 base target —
// tcgen05 rejected by this harness's ptxas target), C never materialized.

#define NROWS 8192
#define KDIM  768
#define BM 128
#define BN 256
#define BK 64                  // 64 bf16 = 128B rows
#define NK (KDIM / BK)         // 12
#define NSTAGE 4
#define A_BYTES (BM * BK * 2)  // 16384
#define B_BYTES (BN * BK * 2)  // 32768
#define STAGE_BYTES (A_BYTES + B_BYTES)       // 49152
#define SMEM_TOTAL (NSTAGE * STAGE_BYTES)     // 196608

__device__ __align__(128) __nv_bfloat16 g_Xn[NROWS * KDIM];
__device__ __align__(128) __nv_bfloat16 g_Yn[NROWS * KDIM];
__device__ float g_rowmax[NROWS];
__device__ float g_colmax[NROWS];

__device__ __forceinline__ void atomicMaxF(float* addr, float v) {
    if (v >= 0.f) atomicMax((int*)addr, __float_as_int(v));
    else          atomicMin((unsigned int*)addr, __float_as_uint(v));
}
__device__ __forceinline__ uint32_t s2u(const void* p) {
    return (uint32_t)__cvta_generic_to_shared(p);
}

// ---------------------------------------------------------------------------
// Kernel 1: row-normalize fp32 -> bf16
// ---------------------------------------------------------------------------
__global__ __launch_bounds__(256) void norm_kernel(const float* __restrict__ ex,
                                                   const float* __restrict__ ey) {
    int b = blockIdx.x;
    const float* src;
    __nv_bfloat16* dst;
    if (b < NROWS) { src = ex + (size_t)b * KDIM; dst = g_Xn + (size_t)b * KDIM; }
    else           { b -= NROWS; src = ey + (size_t)b * KDIM; dst = g_Yn + (size_t)b * KDIM; }

    int tid = threadIdx.x;
    float4 v = make_float4(0.f, 0.f, 0.f, 0.f);
    float ss = 0.f;
    if (tid < 192) {
        v = ((const float4*)src)[tid];
        ss = v.x * v.x + v.y * v.y + v.z * v.z + v.w * v.w;
    }
    #pragma unroll
    for (int o = 16; o > 0; o >>= 1) ss += __shfl_xor_sync(0xffffffffu, ss, o);
    __shared__ float wsum[8];
    if ((tid & 31) == 0) wsum[tid >> 5] = ss;
    __syncthreads();
    float tot = wsum[0] + wsum[1] + wsum[2] + wsum[3] +
                wsum[4] + wsum[5] + wsum[6] + wsum[7];
    float inv = 1.0f / fmaxf(sqrtf(tot), 1e-8f);
    if (tid < 192) {
        dst[tid * 4 + 0] = __float2bfloat16(v.x * inv);
        dst[tid * 4 + 1] = __float2bfloat16(v.y * inv);
        dst[tid * 4 + 2] = __float2bfloat16(v.z * inv);
        dst[tid * 4 + 3] = __float2bfloat16(v.w * inv);
    }
}

__global__ void init_kernel() {
    int t = blockIdx.x * blockDim.x + threadIdx.x;
    if (t < NROWS) { g_rowmax[t] = -2.f; g_colmax[t] = -2.f; }
}

// ---------------------------------------------------------------------------
// Kernel 3: bf16 GEMM via mma.sync + ldmatrix, 128x256 CTA tile, 64x64 warp
// tile, BK=64, 4-stage cp.async pipeline, fused row/col max.
// Smem layout per tile row: 128B, XOR-swizzled in 16B units:
//   sw(row, kh) = row*128 + (kh ^ (row & 7)) * 16
// ---------------------------------------------------------------------------
__global__ __launch_bounds__(256, 1) void gemm_max_kernel() {
    extern __shared__ __align__(1024) char smem[];
    __shared__ float srow[BM];
    __shared__ float scol[BN];

    const int tid = threadIdx.x;
    const int warp = tid >> 5, lane = tid & 31;
    const int m0 = blockIdx.y * BM;
    const int n0 = blockIdx.x * BN;
    const int wm = (warp >> 2) * 64;   // warp M base (0 or 64)
    const int wn = (warp & 3) * 64;    // warp N base (0,64,128,192)

    if (tid < BM) srow[tid] = -2.f;
    scol[tid] = -2.f;

    float acc[4][8][4];
    #pragma unroll
    for (int a = 0; a < 4; a++)
        #pragma unroll
        for (int b = 0; b < 8; b++)
            #pragma unroll
            for (int c = 0; c < 4; c++) acc[a][b][c] = 0.f;

    auto prefetch = [&](int stage, int k0, bool valid) {
        if (valid) {
            char* sa = smem + stage * STAGE_BYTES;
            char* sb = sa + A_BYTES;
            #pragma unroll
            for (int j = 0; j < 12; j++) {
                int i = tid + j * 256;  // 0..3071 chunks of 16B
                const __nv_bfloat16* src;
                uint32_t dst;
                if (i < 1024) {         // A: 128 rows x 8 chunks
                    int row = i >> 3, kh = i & 7;
                    src = g_Xn + (size_t)(m0 + row) * KDIM + k0 + kh * 8;
                    dst = s2u(sa + row * 128 + ((kh ^ (row & 7)) << 4));
                } else {                // B: 256 rows x 8 chunks
                    int idx = i - 1024;
                    int row = idx >> 3, kh = idx & 7;
                    src = g_Yn + (size_t)(n0 + row) * KDIM + k0 + kh * 8;
                    dst = s2u(sb + row * 128 + ((kh ^ (row & 7)) << 4));
                }
                asm volatile("cp.async.cg.shared.global [%0], [%1], 16;"
                             :: "r"(dst), "l"(src));
            }
        }
        asm volatile("cp.async.commit_group;");
    };

    prefetch(0, 0, true);
    prefetch(1, BK, true);
    prefetch(2, 2 * BK, true);

    for (int it = 0; it < NK; it++) {
        asm volatile("cp.async.wait_group 2;");
        __syncthreads();
        prefetch((it + 3) & 3, (it + 3) * BK, it + 3 < NK);

        const uint32_t sa = s2u(smem) + (uint32_t)(it & 3) * STAGE_BYTES;
        const uint32_t sb = sa + A_BYTES;

        #pragma unroll
        for (int kk = 0; kk < 4; kk++) {
            uint32_t af[4][4], bf[4][4];
            #pragma unroll
            for (int mt = 0; mt < 4; mt++) {
                int row = wm + mt * 16 + (lane & 15);
                int kh = kk * 2 + (lane >> 4);
                uint32_t addr = sa + row * 128 + ((kh ^ (row & 7)) << 4);
                asm volatile(
                    "ldmatrix.sync.aligned.m8n8.x4.shared.b16 {%0,%1,%2,%3}, [%4];"
                    : "=r"(af[mt][0]), "=r"(af[mt][1]),
                      "=r"(af[mt][2]), "=r"(af[mt][3]) : "r"(addr));
            }
            #pragma unroll
            for (int p = 0; p < 4; p++) {
                int n = wn + p * 16 + ((lane >> 4) << 3) + (lane & 7);
                int kh = kk * 2 + ((lane >> 3) & 1);
                uint32_t addr = sb + n * 128 + ((kh ^ (n & 7)) << 4);
                asm volatile(
                    "ldmatrix.sync.aligned.m8n8.x4.shared.b16 {%0,%1,%2,%3}, [%4];"
                    : "=r"(bf[p][0]), "=r"(bf[p][1]),
                      "=r"(bf[p][2]), "=r"(bf[p][3]) : "r"(addr));
            }
            #pragma unroll
            for (int mt = 0; mt < 4; mt++)
                #pragma unroll
                for (int nt = 0; nt < 8; nt++) {
                    asm volatile(
                        "mma.sync.aligned.m16n8k16.row.col.f32.bf16.bf16.f32 "
                        "{%0,%1,%2,%3}, {%4,%5,%6,%7}, {%8,%9}, {%0,%1,%2,%3};\n"
                        : "+f"(acc[mt][nt][0]), "+f"(acc[mt][nt][1]),
                          "+f"(acc[mt][nt][2]), "+f"(acc[mt][nt][3])
                        : "r"(af[mt][0]), "r"(af[mt][1]),
                          "r"(af[mt][2]), "r"(af[mt][3]),
                          "r"(bf[nt >> 1][(nt & 1) * 2]),
                          "r"(bf[nt >> 1][(nt & 1) * 2 + 1]));
                }
        }
    }
    __syncthreads();

    const int g = lane >> 2, tig = lane & 3;
    // ---- row maxes: row = wm + mt*16 + g + p*8 ----
    #pragma unroll
    for (int mt = 0; mt < 4; mt++)
        #pragma unroll
        for (int p = 0; p < 2; p++) {
            float m = -2.f;
            #pragma unroll
            for (int nt = 0; nt < 8; nt++) {
                m = fmaxf(m, acc[mt][nt][p * 2 + 0]);
                m = fmaxf(m, acc[mt][nt][p * 2 + 1]);
            }
            m = fmaxf(m, __shfl_xor_sync(0xffffffffu, m, 1));
            m = fmaxf(m, __shfl_xor_sync(0xffffffffu, m, 2));
            if (tig == 0) atomicMaxF(&srow[wm + mt * 16 + g + p * 8], m);
        }
    // ---- col maxes: col = wn + nt*8 + tig*2 + q ----
    #pragma unroll
    for (int nt = 0; nt < 8; nt++)
        #pragma unroll
        for (int q = 0; q < 2; q++) {
            float m = -2.f;
            #pragma unroll
            for (int mt = 0; mt < 4; mt++) {
                m = fmaxf(m, acc[mt][nt][q]);
                m = fmaxf(m, acc[mt][nt][2 + q]);
            }
            m = fmaxf(m, __shfl_xor_sync(0xffffffffu, m, 4));
            m = fmaxf(m, __shfl_xor_sync(0xffffffffu, m, 8));
            m = fmaxf(m, __shfl_xor_sync(0xffffffffu, m, 16));
            if (g == 0) atomicMaxF(&scol[wn + nt * 8 + tig * 2 + q], m);
        }

    __syncthreads();
    if (tid < BM) atomicMaxF(&g_rowmax[m0 + tid], srow[tid]);
    atomicMaxF(&g_colmax[n0 + tid], scol[tid]);
}

// ---------------------------------------------------------------------------
// Kernel 4: finalize entropy terms.
// ---------------------------------------------------------------------------
__global__ __launch_bounds__(256) void final_kernel(float* __restrict__ out) {
    const float LOG_NORM = -0.69579514f;  // -log(0.8) - 0.5*log(2*pi)
    const float INV2S2   = 0.78125f;      // 1 / (2 * 0.8^2)
    int tid = threadIdx.x;
    float s1 = 0.f, s2 = 0.f;
    for (int i = tid; i < NROWS; i += 256) {
        float c = g_rowmax[i];
        float lp = -(c * c) * INV2S2 + LOG_NORM;
        s1 -= expf(lp) * lp;
        c = g_colmax[i];
        lp = -(c * c) * INV2S2 + LOG_NORM;
        s2 -= expf(lp) * lp;
    }
    #pragma unroll
    for (int o = 16; o > 0; o >>= 1) {
        s1 += __shfl_xor_sync(0xffffffffu, s1, o);
        s2 += __shfl_xor_sync(0xffffffffu, s2, o);
    }
    __shared__ float w1[8], w2[8];
    if ((tid & 31) == 0) { w1[tid >> 5] = s1; w2[tid >> 5] = s2; }
    __syncthreads();
    if (tid == 0) {
        float t1 = 0.f, t2 = 0.f;
        #pragma unroll
        for (int i = 0; i < 8; i++) { t1 += w1[i]; t2 += w2[i]; }
        out[0] = t1;
        out[1] = t2;
    }
}

// ---------------------------------------------------------------------------
extern "C" void kernel_launch(void* const* d_in, const int* in_sizes, int n_in,
                              void* d_out, int out_size) {
    (void)in_sizes; (void)n_in; (void)out_size;
    const float* ex = (const float*)d_in[0];
    const float* ey = (const float*)d_in[1];
    float* out = (float*)d_out;

    cudaFuncSetAttribute(gemm_max_kernel,
                         cudaFuncAttributeMaxDynamicSharedMemorySize, SMEM_TOTAL);

    norm_kernel<<<2 * NROWS, 256>>>(ex, ey);
    init_kernel<<<(NROWS + 255) / 256, 256>>>();
    dim3 grid(NROWS / BN, NROWS / BM);   // 32 x 64
    gemm_max_kernel<<<grid, 256, SMEM_TOTAL>>>();
    final_kernel<<<1, 256>>>(out);
}